// round 13
// baseline (speedup 1.0000x reference)
#include <cuda_runtime.h>

#define BATCH 16
#define CIN   768
#define L0    4096
#define L1    2048
#define L2    1024

__device__ float g_h1[BATCH * 32 * L1];
__device__ float g_A[BATCH * 64 * L2];
__device__ float g_B[BATCH * 64 * L2];
__device__ float g_C[BATCH * 64 * L2];
__device__ float g_d1[BATCH * 32 * L1];
__device__ float g_e2[512];
// conv1 weights, fragment-permuted, hi/lo tf32 split: [384 s][2 ct][32 lane][4 j]
__device__ float g_wph[384 * 2 * 32 * 4];
__device__ float g_wpl[384 * 2 * 32 * 4];

__device__ __forceinline__ float tf32r(float v) {
    unsigned r; asm("cvt.rna.tf32.f32 %0,%1;" : "=r"(r) : "f"(v));
    return __uint_as_float(r);
}
__device__ __forceinline__ void mma8(float* d, float4 A, unsigned b0, unsigned b1) {
    unsigned a0 = __float_as_uint(A.x), a1 = __float_as_uint(A.y);
    unsigned a2 = __float_as_uint(A.z), a3 = __float_as_uint(A.w);
    asm volatile(
        "mma.sync.aligned.m16n8k8.row.col.f32.tf32.tf32.f32 "
        "{%0,%1,%2,%3},{%4,%5,%6,%7},{%8,%9},{%0,%1,%2,%3};"
        : "+f"(d[0]), "+f"(d[1]), "+f"(d[2]), "+f"(d[3])
        : "r"(a0), "r"(a1), "r"(a2), "r"(a3), "r"(b0), "r"(b1));
}

// ---- conv1 weight prep: permute into fragment order, hi/lo split -----------
__global__ __launch_bounds__(256) void conv1_prep(const float* __restrict__ w) {
    int i = blockIdx.x * 256 + threadIdx.x;      // 384*2*32*4 = 98304
    int j = i & 3, lane = (i >> 2) & 31, ct = (i >> 7) & 1, s = i >> 8;
    int o = ct * 16 + (lane >> 2) + (j & 1) * 8;
    int k = (lane & 3) + (j >> 1) * 4;
    int c = 2 * s + (k >> 2), tap = k & 3;
    float v = w[(o * CIN + c) * 4 + tap];
    float h = tf32r(v);
    g_wph[i] = h;
    g_wpl[i] = tf32r(v - h);
}

// ---- conv1 main: register-direct 3xTF32 MMA, 16 n-positions per warp -------
// grid (16, 16): 128 positions/block, warp w covers t0+16w .. t0+16w+15.
__global__ __launch_bounds__(256) void conv1_mma(const float* __restrict__ x,
                                                 const float* __restrict__ bias) {
    const int bb = blockIdx.y, t0 = blockIdx.x * 128;
    const int lane = threadIdx.x & 31;
    const int w16 = (threadIdx.x >> 5) * 16;
    const int tb = t0 + w16 + (lane >> 2);       // B-frag position for set 0
    const int gp0 = 2 * tb - 1 + (lane & 3);     // input pos (loop-invariant)
    const int gp1 = gp0 + 16;                    // set 1 (positions +8)
    const bool ok0 = (gp0 >= 0) && (gp0 < L0);
    const bool ok1 = (gp1 < L0);                 // gp1 >= 15 always
    const float* xb = x + (size_t)bb * CIN * L0;
    const float4* Ah = (const float4*)g_wph;
    const float4* Al = (const float4*)g_wpl;

    float acc[2][2][4];
#pragma unroll
    for (int ct = 0; ct < 2; ct++)
#pragma unroll
        for (int ss = 0; ss < 2; ss++)
#pragma unroll
            for (int j = 0; j < 4; j++) acc[ct][ss][j] = 0.f;

#pragma unroll 2
    for (int s = 0; s < 384; ++s) {
        const float* xr = xb + (size_t)(2 * s) * L0;
        float v00 = ok0 ? xr[gp0] : 0.f;
        float v01 = ok0 ? xr[L0 + gp0] : 0.f;
        float v10 = ok1 ? xr[gp1] : 0.f;
        float v11 = ok1 ? xr[L0 + gp1] : 0.f;
        float h00 = tf32r(v00), l00 = tf32r(v00 - h00);
        float h01 = tf32r(v01), l01 = tf32r(v01 - h01);
        float h10 = tf32r(v10), l10 = tf32r(v10 - h10);
        float h11 = tf32r(v11), l11 = tf32r(v11 - h11);
        unsigned bh00 = __float_as_uint(h00), bh01 = __float_as_uint(h01);
        unsigned bl00 = __float_as_uint(l00), bl01 = __float_as_uint(l01);
        unsigned bh10 = __float_as_uint(h10), bh11 = __float_as_uint(h11);
        unsigned bl10 = __float_as_uint(l10), bl11 = __float_as_uint(l11);
#pragma unroll
        for (int ct = 0; ct < 2; ct++) {
            float4 AH = Ah[(s * 2 + ct) * 32 + lane];
            float4 AL = Al[(s * 2 + ct) * 32 + lane];
            mma8(acc[ct][0], AH, bh00, bh01);
            mma8(acc[ct][0], AH, bl00, bl01);
            mma8(acc[ct][0], AL, bh00, bh01);
            mma8(acc[ct][1], AH, bh10, bh11);
            mma8(acc[ct][1], AH, bl10, bl11);
            mma8(acc[ct][1], AL, bh10, bh11);
        }
    }
    const int gr = lane >> 2;
#pragma unroll
    for (int ss = 0; ss < 2; ss++) {
        const int t = t0 + w16 + 8 * ss + 2 * (lane & 3);
#pragma unroll
        for (int ct = 0; ct < 2; ct++) {
            int o0 = ct * 16 + gr, o1 = o0 + 8;
            float b0 = bias[o0], b1 = bias[o1];
            g_h1[((size_t)bb * 32 + o0) * L1 + t]     = fmaxf(acc[ct][ss][0] + b0, 0.f);
            g_h1[((size_t)bb * 32 + o0) * L1 + t + 1] = fmaxf(acc[ct][ss][1] + b0, 0.f);
            g_h1[((size_t)bb * 32 + o1) * L1 + t]     = fmaxf(acc[ct][ss][2] + b1, 0.f);
            g_h1[((size_t)bb * 32 + o1) * L1 + t + 1] = fmaxf(acc[ct][ss][3] + b1, 0.f);
        }
    }
}

// ---- conv2: h1->out(16,64,1024), k4 s2 p1, ReLU ----------------------------
__global__ __launch_bounds__(256) void conv2_k(const float* __restrict__ w,
                                               const float* __restrict__ bias,
                                               float* __restrict__ out) {
    extern __shared__ float sm[];
    float* xs = sm;               // [32][132]
    float* ws = sm + 32 * 132;    // [32*4][68]
    const int b = blockIdx.y, t0 = blockIdx.x * 64;
    const int tid = threadIdx.x, lane = tid & 31, og = tid >> 5;
    float acc[8][2];
#pragma unroll
    for (int i = 0; i < 8; i++) { acc[i][0] = 0.f; acc[i][1] = 0.f; }

    for (int i = tid; i < 64 * 32 * 4; i += 256) {
        int k = i & 3, c = (i >> 2) & 31, o = i >> 7;
        ws[(c * 4 + k) * 68 + o] = w[((o * 32) + c) * 4 + k];
    }
    for (int i = tid; i < 32 * 130; i += 256) {
        int c = i / 130, p = i - c * 130;
        int gp = 2 * t0 - 1 + p;
        xs[c * 132 + p] = (gp >= 0 && gp < L1) ? g_h1[((b * 32) + c) * L1 + gp] : 0.f;
    }
    __syncthreads();
#pragma unroll 4
    for (int c = 0; c < 32; ++c) {
        float wr[4][8];
#pragma unroll
        for (int k = 0; k < 4; k++) {
            float4 a  = *(const float4*)&ws[(c * 4 + k) * 68 + og * 8];
            float4 b4 = *(const float4*)&ws[(c * 4 + k) * 68 + og * 8 + 4];
            wr[k][0] = a.x;  wr[k][1] = a.y;  wr[k][2] = a.z;  wr[k][3] = a.w;
            wr[k][4] = b4.x; wr[k][5] = b4.y; wr[k][6] = b4.z; wr[k][7] = b4.w;
        }
#pragma unroll
        for (int tj = 0; tj < 2; tj++) {
            const float* xr = &xs[c * 132 + 2 * (lane + 32 * tj)];
            float x0 = xr[0], x1 = xr[1], x2 = xr[2], x3 = xr[3];
#pragma unroll
            for (int oi = 0; oi < 8; oi++)
                acc[oi][tj] += wr[0][oi] * x0 + wr[1][oi] * x1 + wr[2][oi] * x2 + wr[3][oi] * x3;
        }
    }
#pragma unroll
    for (int oi = 0; oi < 8; oi++) {
        int o = og * 8 + oi;
        float bv = bias[o];
#pragma unroll
        for (int tj = 0; tj < 2; tj++)
            out[((b * 64) + o) * L2 + t0 + lane + 32 * tj] = fmaxf(acc[oi][tj] + bv, 0.f);
    }
}

// ---- generic conv 64->64, stride1, pad K/2, tile 64 ------------------------
template <int K>
__global__ __launch_bounds__(256) void gconv_k(const float* __restrict__ in,
                                               float* __restrict__ out,
                                               const float* __restrict__ w,
                                               const float* __restrict__ bias) {
    extern __shared__ float sm[];
    constexpr int H = K / 2, W = 64 + 2 * H;
    float* xs = sm;               // [64][68]
    float* ws = sm + 64 * 68;     // [64*K][68]
    const int b = blockIdx.y, t0 = blockIdx.x * 64;
    const int tid = threadIdx.x, lane = tid & 31, og = tid >> 5;
    float acc[8][2];
#pragma unroll
    for (int i = 0; i < 8; i++) { acc[i][0] = 0.f; acc[i][1] = 0.f; }

    for (int i = tid; i < 64 * 64 * K; i += 256) {
        int k = i % K, r = i / K, c = r & 63, o = r >> 6;
        ws[(c * K + k) * 68 + o] = w[(o * 64 + c) * K + k];
    }
    for (int i = tid; i < 64 * W; i += 256) {
        int c = i / W, p = i - c * W;
        int gp = t0 - H + p;
        xs[c * 68 + p] = (gp >= 0 && gp < L2) ? in[((b * 64) + c) * L2 + gp] : 0.f;
    }
    __syncthreads();
#pragma unroll 2
    for (int c = 0; c < 64; ++c) {
        float wr[K][8];
#pragma unroll
        for (int k = 0; k < K; k++) {
            float4 a  = *(const float4*)&ws[(c * K + k) * 68 + og * 8];
            float4 b4 = *(const float4*)&ws[(c * K + k) * 68 + og * 8 + 4];
            wr[k][0] = a.x;  wr[k][1] = a.y;  wr[k][2] = a.z;  wr[k][3] = a.w;
            wr[k][4] = b4.x; wr[k][5] = b4.y; wr[k][6] = b4.z; wr[k][7] = b4.w;
        }
#pragma unroll
        for (int tj = 0; tj < 2; tj++) {
            const float* xr = &xs[c * 68 + lane + 32 * tj];
#pragma unroll
            for (int oi = 0; oi < 8; oi++) {
                float s = 0.f;
#pragma unroll
                for (int k = 0; k < K; k++) s += wr[k][oi] * xr[k];
                acc[oi][tj] += s;
            }
        }
    }
#pragma unroll
    for (int oi = 0; oi < 8; oi++) {
        int o = og * 8 + oi;
        float bv = bias[o];
#pragma unroll
        for (int tj = 0; tj < 2; tj++)
            out[((b * 64) + o) * L2 + t0 + lane + 32 * tj] = acc[oi][tj] + bv;
    }
}

// ---- fused residual block, tile 64 (R11 form) ------------------------------
__global__ __launch_bounds__(256) void res_k(const float* __restrict__ in,
                                             float* __restrict__ out,
                                             const float* __restrict__ w1,
                                             const float* __restrict__ w2,
                                             int relu_out) {
    extern __shared__ float sm[];
    float* xr  = sm;                  // [64][68] relu(in) with halo 1
    float* w1s = xr + 64 * 68;        // [64c*3k][36]
    float* w2s = w1s + 64 * 3 * 36;   // [32c][68]
    float* hs  = w2s + 32 * 68;       // [32][66]
    const int bb = blockIdx.y, t0 = blockIdx.x * 64;
    const int tid = threadIdx.x, lane = tid & 31, og = tid >> 5;

    for (int i = tid; i < 64 * 3 * 32; i += 256) {
        int k = i % 3, r = i / 3, c = r & 63, o = r >> 6;
        w1s[(c * 3 + k) * 36 + o] = w1[(o * 64 + c) * 3 + k];
    }
    for (int i = tid; i < 32 * 64; i += 256) {
        int c = i >> 6, o = i & 63;
        w2s[c * 68 + o] = w2[o * 32 + c];
    }
    for (int i = tid; i < 64 * 66; i += 256) {
        int c = i / 66, p = i - c * 66;
        int gp = t0 - 1 + p;
        float v = (gp >= 0 && gp < L2) ? in[((bb * 64) + c) * L2 + gp] : 0.f;
        xr[c * 68 + p] = fmaxf(v, 0.f);
    }
    __syncthreads();
    {   // phase 1: h = relu(conv3(relu(in))), 32 mid channels
        float a1[4][2];
#pragma unroll
        for (int i = 0; i < 4; i++) { a1[i][0] = 0.f; a1[i][1] = 0.f; }
#pragma unroll 2
        for (int c = 0; c < 64; ++c) {
            float wr[3][4];
#pragma unroll
            for (int k = 0; k < 3; k++) {
                float4 a = *(const float4*)&w1s[(c * 3 + k) * 36 + og * 4];
                wr[k][0] = a.x; wr[k][1] = a.y; wr[k][2] = a.z; wr[k][3] = a.w;
            }
#pragma unroll
            for (int tj = 0; tj < 2; tj++) {
                const float* xp = &xr[c * 68 + lane + 32 * tj];
                float x0 = xp[0], x1 = xp[1], x2 = xp[2];
#pragma unroll
                for (int oi = 0; oi < 4; oi++)
                    a1[oi][tj] += wr[0][oi] * x0 + wr[1][oi] * x1 + wr[2][oi] * x2;
            }
        }
#pragma unroll
        for (int oi = 0; oi < 4; oi++)
#pragma unroll
            for (int tj = 0; tj < 2; tj++)
                hs[(og * 4 + oi) * 66 + lane + 32 * tj] = fmaxf(a1[oi][tj], 0.f);
    }
    __syncthreads();
    {   // phase 2: out = in + w2 @ h
        float a2[8][2];
#pragma unroll
        for (int i = 0; i < 8; i++) { a2[i][0] = 0.f; a2[i][1] = 0.f; }
#pragma unroll 4
        for (int c = 0; c < 32; ++c) {
            float4 a  = *(const float4*)&w2s[c * 68 + og * 8];
            float4 b4 = *(const float4*)&w2s[c * 68 + og * 8 + 4];
            float wr[8] = {a.x, a.y, a.z, a.w, b4.x, b4.y, b4.z, b4.w};
#pragma unroll
            for (int tj = 0; tj < 2; tj++) {
                float hv = hs[c * 66 + lane + 32 * tj];
#pragma unroll
                for (int oi = 0; oi < 8; oi++) a2[oi][tj] += wr[oi] * hv;
            }
        }
#pragma unroll
        for (int oi = 0; oi < 8; oi++) {
            int o = og * 8 + oi;
#pragma unroll
            for (int tj = 0; tj < 2; tj++) {
                int t = t0 + lane + 32 * tj;
                float v = in[((bb * 64) + o) * L2 + t] + a2[oi][tj];
                if (relu_out) v = fmaxf(v, 0.f);
                out[((bb * 64) + o) * L2 + t] = v;
            }
        }
    }
}

// ---- codebook squared norms ------------------------------------------------
__global__ void e2_k(const float* __restrict__ emb) {
    int c = blockIdx.x * blockDim.x + threadIdx.x;
    if (c < 512) {
        float s = 0.f;
#pragma unroll 8
        for (int d = 0; d < 64; ++d) { float v = emb[c * 64 + d]; s += v * v; }
        g_e2[c] = s;
    }
}

// ---- VQ: nearest codebook row per (b,t) ------------------------------------
__global__ __launch_bounds__(256) void vq_k(const float* __restrict__ z,
                                            float* __restrict__ q,
                                            const float* __restrict__ emb) {
    extern __shared__ float sm[];
    float* zs  = sm;              // [64][33]
    float* es  = zs + 64 * 33;    // [512][17]
    float* e2s = es + 512 * 17;   // [512]
    __shared__ int idxs[32];
    const int v0 = blockIdx.x * 32;
    const int b = v0 >> 10, t0 = v0 & 1023;
    const int tid = threadIdx.x, lane = tid & 31, vg = tid >> 5;

    for (int i = tid; i < 64 * 32; i += 256) {
        int d = i >> 5, vv = i & 31;
        zs[d * 33 + vv] = z[((b * 64) + d) * L2 + t0 + vv];
    }
    for (int i = tid; i < 512; i += 256) e2s[i] = g_e2[i];

    float acc[4][16];
#pragma unroll
    for (int i = 0; i < 4; i++)
#pragma unroll
        for (int j = 0; j < 16; j++) acc[i][j] = 0.f;

    for (int k0 = 0; k0 < 64; k0 += 16) {
        __syncthreads();
        for (int i = tid; i < 512 * 4; i += 256) {
            int c = i >> 2, kq = i & 3;
            float4 v = *(const float4*)&emb[c * 64 + k0 + kq * 4];
            float* d = &es[c * 17 + kq * 4];
            d[0] = v.x; d[1] = v.y; d[2] = v.z; d[3] = v.w;
        }
        __syncthreads();
#pragma unroll
        for (int kd = 0; kd < 16; ++kd) {
            float zv0 = zs[(k0 + kd) * 33 + vg * 4 + 0];
            float zv1 = zs[(k0 + kd) * 33 + vg * 4 + 1];
            float zv2 = zs[(k0 + kd) * 33 + vg * 4 + 2];
            float zv3 = zs[(k0 + kd) * 33 + vg * 4 + 3];
#pragma unroll
            for (int cc = 0; cc < 16; ++cc) {
                float ev = es[(lane + 32 * cc) * 17 + kd];
                acc[0][cc] += zv0 * ev;
                acc[1][cc] += zv1 * ev;
                acc[2][cc] += zv2 * ev;
                acc[3][cc] += zv3 * ev;
            }
        }
    }
#pragma unroll
    for (int vv = 0; vv < 4; ++vv) {
        float mv = 3.0e38f; int mi = 0;
#pragma unroll
        for (int cc = 0; cc < 16; ++cc) {
            int c = lane + 32 * cc;
            float val = e2s[c] - 2.0f * acc[vv][cc];
            if (val < mv) { mv = val; mi = c; }
        }
        for (int off = 16; off > 0; off >>= 1) {
            float ov = __shfl_down_sync(0xffffffffu, mv, off);
            int   oi = __shfl_down_sync(0xffffffffu, mi, off);
            if (ov < mv || (ov == mv && oi < mi)) { mv = ov; mi = oi; }
        }
        if (lane == 0) idxs[vg * 4 + vv] = mi;
    }
    __syncthreads();
    for (int i = tid; i < 64 * 32; i += 256) {
        int d = i >> 5, vv = i & 31;
        q[((b * 64) + d) * L2 + t0 + vv] = emb[idxs[vv] * 64 + d];
    }
}

// ---- dect1: ConvTranspose1d 64->32, k4 s2 p1, bias, ReLU -------------------
__global__ __launch_bounds__(256) void dect1_k(const float* __restrict__ in,
                                               const float* __restrict__ w,
                                               const float* __restrict__ bias) {
    extern __shared__ float sm[];
    float* xs = sm;               // [64][68]
    float* ws = sm + 64 * 68;     // [64c*4k][36]
    const int b = blockIdx.y, t0 = blockIdx.x * 128;
    const int tid = threadIdx.x, lane = tid & 31, og = tid >> 5;
    const int s0 = t0 / 2 - 1;
    float acc[4][4];
#pragma unroll
    for (int i = 0; i < 4; i++)
#pragma unroll
        for (int j = 0; j < 4; j++) acc[i][j] = 0.f;

    for (int i = tid; i < 64 * 32 * 4; i += 256) {
        int k = i & 3, o = (i >> 2) & 31, c = i >> 7;
        ws[(c * 4 + k) * 36 + o] = w[((c * 32) + o) * 4 + k];
    }
    for (int i = tid; i < 64 * 66; i += 256) {
        int c = i / 66, ls = i - c * 66;
        int s = s0 + ls;
        xs[c * 68 + ls] = (s >= 0 && s < L2) ? in[((b * 64) + c) * L2 + s] : 0.f;
    }
    __syncthreads();
    const int khi = (lane & 1) ? 0 : 1;
    const int klo = khi + 2;
    const int lsb = ((lane + (lane & 1)) >> 1) + 1;
#pragma unroll 2
    for (int c = 0; c < 64; ++c) {
        float4 wh = *(const float4*)&ws[(c * 4 + khi) * 36 + og * 4];
        float4 wl = *(const float4*)&ws[(c * 4 + klo) * 36 + og * 4];
#pragma unroll
        for (int tj = 0; tj < 4; tj++) {
            int lh = lsb + 16 * tj;
            float xh = xs[c * 68 + lh], xl = xs[c * 68 + lh - 1];
            acc[0][tj] += wh.x * xh + wl.x * xl;
            acc[1][tj] += wh.y * xh + wl.y * xl;
            acc[2][tj] += wh.z * xh + wl.z * xl;
            acc[3][tj] += wh.w * xh + wl.w * xl;
        }
    }
#pragma unroll
    for (int oi = 0; oi < 4; oi++) {
        int o = og * 4 + oi;
        float bv = bias[o];
#pragma unroll
        for (int tj = 0; tj < 4; tj++)
            g_d1[((b * 32) + o) * L1 + t0 + lane + 32 * tj] = fmaxf(acc[oi][tj] + bv, 0.f);
    }
}

// ---- dect2: ConvTranspose1d 32->64, k4 s2 p1, bias -> d_out ----------------
__global__ __launch_bounds__(256) void dect2_k(const float* __restrict__ w,
                                               const float* __restrict__ bias,
                                               float* __restrict__ out) {
    extern __shared__ float sm[];
    float* xs = sm;               // [32][68]
    float* ws = sm + 32 * 68;     // [32c*4k][68]
    const int b = blockIdx.y, t0 = blockIdx.x * 128;
    const int tid = threadIdx.x, lane = tid & 31, og = tid >> 5;
    const int s0 = t0 / 2 - 1;
    float acc[8][4];
#pragma unroll
    for (int i = 0; i < 8; i++)
#pragma unroll
        for (int j = 0; j < 4; j++) acc[i][j] = 0.f;

    for (int i = tid; i < 32 * 64 * 4; i += 256) {
        int k = i & 3, o = (i >> 2) & 63, c = i >> 8;
        ws[(c * 4 + k) * 68 + o] = w[((c * 64) + o) * 4 + k];
    }
    for (int i = tid; i < 32 * 66; i += 256) {
        int c = i / 66, ls = i - c * 66;
        int s = s0 + ls;
        xs[c * 68 + ls] = (s >= 0 && s < L1) ? g_d1[((b * 32) + c) * L1 + s] : 0.f;
    }
    __syncthreads();
    const int khi = (lane & 1) ? 0 : 1;
    const int klo = khi + 2;
    const int lsb = ((lane + (lane & 1)) >> 1) + 1;
#pragma unroll 2
    for (int c = 0; c < 32; ++c) {
        float4 wh0 = *(const float4*)&ws[(c * 4 + khi) * 68 + og * 8];
        float4 wh1 = *(const float4*)&ws[(c * 4 + khi) * 68 + og * 8 + 4];
        float4 wl0 = *(const float4*)&ws[(c * 4 + klo) * 68 + og * 8];
        float4 wl1 = *(const float4*)&ws[(c * 4 + klo) * 68 + og * 8 + 4];
        float wh[8] = {wh0.x, wh0.y, wh0.z, wh0.w, wh1.x, wh1.y, wh1.z, wh1.w};
        float wl[8] = {wl0.x, wl0.y, wl0.z, wl0.w, wl1.x, wl1.y, wl1.z, wl1.w};
#pragma unroll
        for (int tj = 0; tj < 4; tj++) {
            int lh = lsb + 16 * tj;
            float xh = xs[c * 68 + lh], xl = xs[c * 68 + lh - 1];
#pragma unroll
            for (int oi = 0; oi < 8; oi++)
                acc[oi][tj] += wh[oi] * xh + wl[oi] * xl;
        }
    }
#pragma unroll
    for (int oi = 0; oi < 8; oi++) {
        int o = og * 8 + oi;
        float bv = bias[o];
#pragma unroll
        for (int tj = 0; tj < 4; tj++)
            out[((b * 64) + o) * L0 + t0 + lane + 32 * tj] = acc[oi][tj] + bv;
    }
}

extern "C" void kernel_launch(void* const* d_in, const int* in_sizes, int n_in,
                              void* d_out, int out_size) {
    const float* x         = (const float*)d_in[0];
    const float* enc_w1    = (const float*)d_in[1];
    const float* enc_b1    = (const float*)d_in[2];
    const float* enc_w2    = (const float*)d_in[3];
    const float* enc_b2    = (const float*)d_in[4];
    const float* enc_w3    = (const float*)d_in[5];
    const float* enc_b3    = (const float*)d_in[6];
    const float* enc_r0_w1 = (const float*)d_in[7];
    const float* enc_r0_w2 = (const float*)d_in[8];
    const float* enc_r1_w1 = (const float*)d_in[9];
    const float* enc_r1_w2 = (const float*)d_in[10];
    const float* prevq_w   = (const float*)d_in[11];
    const float* prevq_b   = (const float*)d_in[12];
    const float* emb       = (const float*)d_in[13];
    const float* dec_w1    = (const float*)d_in[14];
    const float* dec_b1    = (const float*)d_in[15];
    const float* dec_r0_w1 = (const float*)d_in[16];
    const float* dec_r0_w2 = (const float*)d_in[17];
    const float* dec_r1_w1 = (const float*)d_in[18];
    const float* dec_r1_w2 = (const float*)d_in[19];
    const float* dect1_w   = (const float*)d_in[20];
    const float* dect1_b   = (const float*)d_in[21];
    const float* dect2_w   = (const float*)d_in[22];
    const float* dect2_b   = (const float*)d_in[23];
    float* out = (float*)d_out;

    float *A, *B, *C;
    cudaGetSymbolAddress((void**)&A, g_A);
    cudaGetSymbolAddress((void**)&B, g_B);
    cudaGetSymbolAddress((void**)&C, g_C);

    cudaFuncSetAttribute(conv2_k, cudaFuncAttributeMaxDynamicSharedMemorySize, 65536);
    cudaFuncSetAttribute(gconv_k<3>, cudaFuncAttributeMaxDynamicSharedMemorySize, 98304);
    cudaFuncSetAttribute(gconv_k<1>, cudaFuncAttributeMaxDynamicSharedMemorySize, 65536);
    cudaFuncSetAttribute(res_k, cudaFuncAttributeMaxDynamicSharedMemorySize, 65536);
    cudaFuncSetAttribute(dect1_k, cudaFuncAttributeMaxDynamicSharedMemorySize, 65536);

    dim3 blk(256);
    size_t sm_c2  = (32 * 132 + 128 * 68) * 4;
    size_t sm_g3  = (64 * 68 + 64 * 3 * 68) * 4;
    size_t sm_g1  = (64 * 68 + 64 * 68) * 4;
    size_t sm_res = (64 * 68 + 64 * 3 * 36 + 32 * 68 + 32 * 66) * 4;
    size_t sm_vq  = (64 * 33 + 512 * 17 + 512) * 4;
    size_t sm_d1  = (64 * 68 + 256 * 36) * 4;
    size_t sm_d2  = (32 * 68 + 128 * 68) * 4;
    dim3 gg64(L2 / 64, BATCH);

    // encoder
    conv1_prep<<<384, 256>>>(enc_w1);
    conv1_mma<<<dim3(L1 / 128, BATCH), blk>>>(x, enc_b1);
    conv2_k<<<gg64, blk, sm_c2>>>(enc_w2, enc_b2, A);
    gconv_k<3><<<gg64, blk, sm_g3>>>(A, B, enc_w3, enc_b3);
    res_k<<<gg64, blk, sm_res>>>(B, A, enc_r0_w1, enc_r0_w2, 0);
    res_k<<<gg64, blk, sm_res>>>(A, B, enc_r1_w1, enc_r1_w2, 1);
    gconv_k<1><<<gg64, blk, sm_g1>>>(B, A, prevq_w, prevq_b);
    // VQ
    e2_k<<<2, 256>>>(emb);
    vq_k<<<BATCH * L2 / 32, blk, sm_vq>>>(A, C, emb);
    // decoder
    gconv_k<3><<<gg64, blk, sm_g3>>>(C, A, dec_w1, dec_b1);
    res_k<<<gg64, blk, sm_res>>>(A, B, dec_r0_w1, dec_r0_w2, 0);
    res_k<<<gg64, blk, sm_res>>>(B, A, dec_r1_w1, dec_r1_w2, 1);
    dect1_k<<<dim3(L1 / 128, BATCH), blk, sm_d1>>>(A, dect1_w, dect1_b);
    dect2_k<<<dim3(L0 / 128, BATCH), blk, sm_d2>>>(dect2_w, dect2_b, out);
}